// round 11
// baseline (speedup 1.0000x reference)
#include <cuda_runtime.h>
#include <cstddef>
#include <cstdint>

// Problem constants
#define B_  4
#define N_  4096        // H*W
#define C_  512
#define C1_ 960
#define CHUNK 2048      // attention row-chunk
#define EPS_NORM 1e-5f
#define EPS_VAR  1e-9f

// ---------------------------------------------------------------------------
// Static scratch ~73 MB (single-batch QKV reuse + chunked A). Keep small:
// large __device__ bss loads inside the harness mem checkpoint (R2-R7).
// ---------------------------------------------------------------------------
__device__ float g_Q[(size_t)N_ * C1_];        // 15.7 MB
__device__ float g_K[(size_t)N_ * C1_];        // 15.7 MB
__device__ float g_V[(size_t)N_ * C_];         //  8.4 MB
__device__ float g_Ablk[(size_t)CHUNK * N_];   // 33.5 MB
__device__ float g_mc [B_ * C_],  g_rc [B_ * C_];
__device__ float g_mcc[B_ * C1_], g_rcc[B_ * C1_];
__device__ float g_mcs[B_ * C1_], g_rcs[B_ * C1_];

// ---------------------------------------------------------------------------
// Per-(batch, channel) spatial mean / rstd.
// ---------------------------------------------------------------------------
template<int WHICH>
__global__ void stats_kernel(const float* __restrict__ x, int Cx)
{
    int c = blockIdx.x * 32 + threadIdx.x;
    int b = blockIdx.y;
    const float* xb = x + (size_t)b * N_ * Cx;
    float s = 0.f, s2 = 0.f;
    for (int n = threadIdx.y; n < N_; n += 16) {
        float v = xb[(size_t)n * Cx + c];
        s  += v;
        s2 += v * v;
    }
    __shared__ float sh_s [16][33];
    __shared__ float sh_s2[16][33];
    sh_s [threadIdx.y][threadIdx.x] = s;
    sh_s2[threadIdx.y][threadIdx.x] = s2;
    __syncthreads();
    if (threadIdx.y == 0) {
        #pragma unroll
        for (int i = 1; i < 16; i++) {
            s  += sh_s [i][threadIdx.x];
            s2 += sh_s2[i][threadIdx.x];
        }
        float m   = s * (1.0f / N_);
        float var = s2 * (1.0f / N_) - m * m;
        float r   = rsqrtf(var + EPS_NORM);
        if (WHICH == 0) { g_mc [b * Cx + c] = m; g_rc [b * Cx + c] = r; }
        if (WHICH == 1) { g_mcc[b * Cx + c] = m; g_rcc[b * Cx + c] = r; }
        if (WHICH == 2) { g_mcs[b * Cx + c] = m; g_rcs[b * Cx + c] = r; }
    }
}

// ---------------------------------------------------------------------------
// Projection GEMM, 2-stage pipelined:  DST = norm(A) @ W + bias  (one batch)
// BM=128, BN=128, BK=16, 256 thr, 8x8 microtile, double-buffered smem.
// ---------------------------------------------------------------------------
template<int NORM, int DST>
__global__ __launch_bounds__(256, 2)
void proj_kernel(const float* __restrict__ A,
                 const float* __restrict__ W,
                 const float* __restrict__ bias,
                 int b, int Nn, int K)
{
    __shared__ float As[2][16][128 + 4];
    __shared__ float Bs[2][16][128 + 4];

    float* Cb = (DST == 0) ? g_Q : (DST == 1) ? g_K : g_V;
    const float* mA = (NORM == 1) ? (g_mcc + (size_t)b * K)
                    : (NORM == 2) ? (g_mcs + (size_t)b * K) : nullptr;
    const float* rA = (NORM == 1) ? (g_rcc + (size_t)b * K)
                    : (NORM == 2) ? (g_rcs + (size_t)b * K) : nullptr;

    int m0 = blockIdx.y * 128;
    int n0 = blockIdx.x * 128;
    int tid = threadIdx.x;
    int a_k = tid & 15, a_m = tid >> 4;       // A loader: k, row-group
    int b_n = tid & 127, b_kk = tid >> 7;     // B loader: col, k-group
    int tc  = tid & 15, tr  = tid >> 4;       // compute

    float a_st[8], b_st[8];
    float acc[8][8];
    #pragma unroll
    for (int i = 0; i < 8; i++)
        #pragma unroll
        for (int j = 0; j < 8; j++) acc[i][j] = 0.f;

    // ---- prologue: tile 0 ----
    {
        float nm = 0.f, nr = 1.f;
        if (NORM) { nm = mA[a_k]; nr = rA[a_k]; }
        #pragma unroll
        for (int i = 0; i < 8; i++) {
            float v = A[(size_t)(m0 + a_m + i * 16) * K + a_k];
            a_st[i] = NORM ? (v - nm) * nr : v;
        }
        #pragma unroll
        for (int i = 0; i < 8; i++)
            b_st[i] = (n0 + b_n < Nn)
                      ? W[(size_t)(b_kk + i * 2) * Nn + n0 + b_n] : 0.f;
        #pragma unroll
        for (int i = 0; i < 8; i++) As[0][a_k][a_m + i * 16] = a_st[i];
        #pragma unroll
        for (int i = 0; i < 8; i++) Bs[0][b_kk + i * 2][b_n] = b_st[i];
    }
    __syncthreads();

    int nT = K / 16;
    for (int t = 0; t < nT; t++) {
        int cur = t & 1;
        if (t + 1 < nT) {                     // issue next tile's LDGs
            int k0 = (t + 1) * 16;
            float nm = 0.f, nr = 1.f;
            if (NORM) { nm = mA[k0 + a_k]; nr = rA[k0 + a_k]; }
            #pragma unroll
            for (int i = 0; i < 8; i++) {
                float v = A[(size_t)(m0 + a_m + i * 16) * K + k0 + a_k];
                a_st[i] = NORM ? (v - nm) * nr : v;
            }
            #pragma unroll
            for (int i = 0; i < 8; i++)
                b_st[i] = (n0 + b_n < Nn)
                          ? W[(size_t)(k0 + b_kk + i * 2) * Nn + n0 + b_n] : 0.f;
        }
        #pragma unroll
        for (int k = 0; k < 16; k++) {        // compute current buffer
            float ra[8], rb[8];
            #pragma unroll
            for (int i = 0; i < 8; i++) ra[i] = As[cur][k][tr * 8 + i];
            #pragma unroll
            for (int j = 0; j < 8; j++) rb[j] = Bs[cur][k][tc * 8 + j];
            #pragma unroll
            for (int i = 0; i < 8; i++)
                #pragma unroll
                for (int j = 0; j < 8; j++)
                    acc[i][j] += ra[i] * rb[j];
        }
        if (t + 1 < nT) {                     // store staged into other buffer
            #pragma unroll
            for (int i = 0; i < 8; i++) As[cur ^ 1][a_k][a_m + i * 16] = a_st[i];
            #pragma unroll
            for (int i = 0; i < 8; i++) Bs[cur ^ 1][b_kk + i * 2][b_n] = b_st[i];
        }
        __syncthreads();
    }

    #pragma unroll
    for (int i = 0; i < 8; i++) {
        int m = m0 + tr * 8 + i;
        #pragma unroll
        for (int j = 0; j < 8; j++) {
            int n = n0 + tc * 8 + j;
            if (n < Nn)
                Cb[(size_t)m * Nn + n] = acc[i][j] + bias[n];
        }
    }
}

// ---------------------------------------------------------------------------
// Logits chunk, pipelined:  g_Ablk = Q[chunk] @ K^T.  Both tiles transpose-
// loaded (k-contiguous). BM=BN=128, BK=16; grid (N/128, CHUNK/128).
// ---------------------------------------------------------------------------
__global__ __launch_bounds__(256, 2)
void qkt_kernel(int mblk)
{
    __shared__ float As[2][16][128 + 4];
    __shared__ float Bs[2][16][128 + 4];

    int mloc0 = blockIdx.y * 128;
    int m0 = mblk * CHUNK + mloc0;
    int n0 = blockIdx.x * 128;
    int tid = threadIdx.x;
    int a_k = tid & 15, a_m = tid >> 4;
    int tc  = tid & 15, tr  = tid >> 4;

    float a_st[8], b_st[8];
    float acc[8][8];
    #pragma unroll
    for (int i = 0; i < 8; i++)
        #pragma unroll
        for (int j = 0; j < 8; j++) acc[i][j] = 0.f;

    {
        #pragma unroll
        for (int i = 0; i < 8; i++) {
            int r = a_m + i * 16;
            a_st[i] = g_Q[(size_t)(m0 + r) * C1_ + a_k];
            b_st[i] = g_K[(size_t)(n0 + r) * C1_ + a_k];
        }
        #pragma unroll
        for (int i = 0; i < 8; i++) {
            As[0][a_k][a_m + i * 16] = a_st[i];
            Bs[0][a_k][a_m + i * 16] = b_st[i];
        }
    }
    __syncthreads();

    const int nT = C1_ / 16;   // 60
    for (int t = 0; t < nT; t++) {
        int cur = t & 1;
        if (t + 1 < nT) {
            int k0 = (t + 1) * 16;
            #pragma unroll
            for (int i = 0; i < 8; i++) {
                int r = a_m + i * 16;
                a_st[i] = g_Q[(size_t)(m0 + r) * C1_ + k0 + a_k];
                b_st[i] = g_K[(size_t)(n0 + r) * C1_ + k0 + a_k];
            }
        }
        #pragma unroll
        for (int k = 0; k < 16; k++) {
            float ra[8], rb[8];
            #pragma unroll
            for (int i = 0; i < 8; i++) ra[i] = As[cur][k][tr * 8 + i];
            #pragma unroll
            for (int j = 0; j < 8; j++) rb[j] = Bs[cur][k][tc * 8 + j];
            #pragma unroll
            for (int i = 0; i < 8; i++)
                #pragma unroll
                for (int j = 0; j < 8; j++)
                    acc[i][j] += ra[i] * rb[j];
        }
        if (t + 1 < nT) {
            #pragma unroll
            for (int i = 0; i < 8; i++) {
                As[cur ^ 1][a_k][a_m + i * 16] = a_st[i];
                Bs[cur ^ 1][a_k][a_m + i * 16] = b_st[i];
            }
        }
        __syncthreads();
    }

    #pragma unroll
    for (int i = 0; i < 8; i++) {
        size_t row = (size_t)(mloc0 + tr * 8 + i) * N_;
        int n = n0 + tc * 8;
        float4 v0, v1;
        v0.x = acc[i][0]; v0.y = acc[i][1]; v0.z = acc[i][2]; v0.w = acc[i][3];
        v1.x = acc[i][4]; v1.y = acc[i][5]; v1.z = acc[i][6]; v1.w = acc[i][7];
        *(float4*)(g_Ablk + row + n)     = v0;
        *(float4*)(g_Ablk + row + n + 4) = v1;
    }
}

// ---------------------------------------------------------------------------
// Row softmax over g_Ablk (CHUNK rows of 4096), in place.
// ---------------------------------------------------------------------------
__global__ __launch_bounds__(256)
void softmax_kernel()
{
    float* a = g_Ablk + (size_t)blockIdx.x * N_;
    int t = threadIdx.x;

    float v[16];
    float mx = -3.0e38f;
    #pragma unroll
    for (int i = 0; i < 16; i++) {
        v[i] = a[t + i * 256];
        mx = fmaxf(mx, v[i]);
    }
    __shared__ float red[256];
    red[t] = mx;
    __syncthreads();
    #pragma unroll
    for (int s = 128; s > 0; s >>= 1) {
        if (t < s) red[t] = fmaxf(red[t], red[t + s]);
        __syncthreads();
    }
    mx = red[0];
    __syncthreads();

    float sum = 0.f;
    #pragma unroll
    for (int i = 0; i < 16; i++) {
        v[i] = __expf(v[i] - mx);
        sum += v[i];
    }
    red[t] = sum;
    __syncthreads();
    #pragma unroll
    for (int s = 128; s > 0; s >>= 1) {
        if (t < s) red[t] += red[t + s];
        __syncthreads();
    }
    float inv = 1.0f / red[0];
    #pragma unroll
    for (int i = 0; i < 16; i++)
        a[t + i * 256] = v[i] * inv;
}

// ---------------------------------------------------------------------------
// Dual GEMM + epilogue, pipelined:
//   M = A@V, E2 = A@(V*V); out = sqrt(max(E2-M*M,eps))*norm(content) + M
// BM=128, BN=64, BK=16; 256 thr; 8x4 dual microtile.
// ---------------------------------------------------------------------------
__global__ __launch_bounds__(256, 2)
void av_epi_kernel(const float* __restrict__ content,
                   float* __restrict__ out, int b, int mblk)
{
    __shared__ float As[2][16][128 + 4];
    __shared__ float Vs[2][16][64];

    int mloc0 = blockIdx.y * 128;
    int n0 = blockIdx.x * 64;
    int tid = threadIdx.x;
    int a_k = tid & 15, a_m = tid >> 4;
    int v_n = tid & 63, v_k = tid >> 6;
    int tc  = tid & 15, tr  = tid >> 4;

    float a_st[8], v_st[4];
    float accM[8][4], accE[8][4];
    #pragma unroll
    for (int i = 0; i < 8; i++)
        #pragma unroll
        for (int j = 0; j < 4; j++) { accM[i][j] = 0.f; accE[i][j] = 0.f; }

    {
        #pragma unroll
        for (int i = 0; i < 8; i++)
            a_st[i] = g_Ablk[(size_t)(mloc0 + a_m + i * 16) * N_ + a_k];
        #pragma unroll
        for (int i = 0; i < 4; i++)
            v_st[i] = g_V[(size_t)(v_k + i * 4) * C_ + n0 + v_n];
        #pragma unroll
        for (int i = 0; i < 8; i++) As[0][a_k][a_m + i * 16] = a_st[i];
        #pragma unroll
        for (int i = 0; i < 4; i++) Vs[0][v_k + i * 4][v_n] = v_st[i];
    }
    __syncthreads();

    const int nT = N_ / 16;    // 256
    for (int t = 0; t < nT; t++) {
        int cur = t & 1;
        if (t + 1 < nT) {
            int k0 = (t + 1) * 16;
            #pragma unroll
            for (int i = 0; i < 8; i++)
                a_st[i] = g_Ablk[(size_t)(mloc0 + a_m + i * 16) * N_ + k0 + a_k];
            #pragma unroll
            for (int i = 0; i < 4; i++)
                v_st[i] = g_V[(size_t)(k0 + v_k + i * 4) * C_ + n0 + v_n];
        }
        #pragma unroll
        for (int k = 0; k < 16; k++) {
            float ra[8], rb[4], rb2[4];
            #pragma unroll
            for (int i = 0; i < 8; i++) ra[i] = As[cur][k][tr * 8 + i];
            #pragma unroll
            for (int j = 0; j < 4; j++) {
                rb[j]  = Vs[cur][k][tc * 4 + j];
                rb2[j] = rb[j] * rb[j];
            }
            #pragma unroll
            for (int i = 0; i < 8; i++)
                #pragma unroll
                for (int j = 0; j < 4; j++) {
                    accM[i][j] += ra[i] * rb[j];
                    accE[i][j] += ra[i] * rb2[j];
                }
        }
        if (t + 1 < nT) {
            #pragma unroll
            for (int i = 0; i < 8; i++) As[cur ^ 1][a_k][a_m + i * 16] = a_st[i];
            #pragma unroll
            for (int i = 0; i < 4; i++) Vs[cur ^ 1][v_k + i * 4][v_n] = v_st[i];
        }
        __syncthreads();
    }

    #pragma unroll
    for (int i = 0; i < 8; i++) {
        int m_global = mblk * CHUNK + mloc0 + tr * 8 + i;
        int c = n0 + tc * 4;
        size_t idx = ((size_t)b * N_ + m_global) * (size_t)C_ + c;
        float oo[4];
        #pragma unroll
        for (int j = 0; j < 4; j++) {
            float Mv = accM[i][j];
            float E2 = accE[i][j];
            float S  = sqrtf(fmaxf(E2 - Mv * Mv, EPS_VAR));
            float nc = (content[idx + j] - g_mc[b * C_ + c + j]) * g_rc[b * C_ + c + j];
            oo[j] = S * nc + Mv;
        }
        float4 o; o.x = oo[0]; o.y = oo[1]; o.z = oo[2]; o.w = oo[3];
        *(float4*)(out + idx) = o;
    }
}

// ---------------------------------------------------------------------------
// Launch — pure kernel launches (graph-capture safe).
// ---------------------------------------------------------------------------
extern "C" void kernel_launch(void* const* d_in, const int* in_sizes, int n_in,
                              void* d_out, int out_size)
{
    const float* content   = (const float*)d_in[0];
    const float* style     = (const float*)d_in[1];
    const float* comb_cont = (const float*)d_in[2];
    const float* comb_sty  = (const float*)d_in[3];
    const float* Wq        = (const float*)d_in[4];
    const float* bq        = (const float*)d_in[5];
    const float* Wk        = (const float*)d_in[6];
    const float* bk        = (const float*)d_in[7];
    const float* Wv        = (const float*)d_in[8];
    const float* bv        = (const float*)d_in[9];
    float* out = (float*)d_out;

    dim3 blk_stats(32, 16);
    stats_kernel<0><<<dim3(C_  / 32, B_), blk_stats>>>(content,   C_);
    stats_kernel<1><<<dim3(C1_ / 32, B_), blk_stats>>>(comb_cont, C1_);
    stats_kernel<2><<<dim3(C1_ / 32, B_), blk_stats>>>(comb_sty,  C1_);

    for (int b = 0; b < B_; b++) {
        proj_kernel<1, 0><<<dim3(8, N_ / 128), 256>>>(
            comb_cont + (size_t)b * N_ * C1_, Wq, bq, b, C1_, C1_);
        proj_kernel<2, 1><<<dim3(8, N_ / 128), 256>>>(
            comb_sty + (size_t)b * N_ * C1_, Wk, bk, b, C1_, C1_);
        proj_kernel<0, 2><<<dim3(4, N_ / 128), 256>>>(
            style + (size_t)b * N_ * C_, Wv, bv, b, C_, C_);

        for (int mblk = 0; mblk < N_ / CHUNK; mblk++) {
            qkt_kernel<<<dim3(N_ / 128, CHUNK / 128), 256>>>(mblk);
            softmax_kernel<<<CHUNK, 256>>>();
            av_epi_kernel<<<dim3(C_ / 64, CHUNK / 128), 256>>>(content, out, b, mblk);
        }
    }
}

// round 12
// speedup vs baseline: 1.0359x; 1.0359x over previous
#include <cuda_runtime.h>
#include <cstddef>
#include <cstdint>

// Problem constants
#define B_  4
#define N_  4096        // H*W
#define C_  512
#define C1_ 960
#define CHUNK 2048      // attention row-chunk
#define EPS_NORM 1e-5f
#define EPS_VAR  1e-9f

// ---------------------------------------------------------------------------
// Static scratch ~73 MB (single-batch QKV reuse + chunked A).
// ---------------------------------------------------------------------------
__device__ float g_Q[(size_t)N_ * C1_];        // 15.7 MB
__device__ float g_K[(size_t)N_ * C1_];        // 15.7 MB
__device__ float g_V[(size_t)N_ * C_];         //  8.4 MB
__device__ float g_Ablk[(size_t)CHUNK * N_];   // 33.5 MB
__device__ float g_mc [B_ * C_],  g_rc [B_ * C_];
__device__ float g_mcc[B_ * C1_], g_rcc[B_ * C1_];
__device__ float g_mcs[B_ * C1_], g_rcs[B_ * C1_];

// ---------------------------------------------------------------------------
// Per-(batch, channel) spatial mean / rstd.
// ---------------------------------------------------------------------------
template<int WHICH>
__global__ void stats_kernel(const float* __restrict__ x, int Cx)
{
    int c = blockIdx.x * 32 + threadIdx.x;
    int b = blockIdx.y;
    const float* xb = x + (size_t)b * N_ * Cx;
    float s = 0.f, s2 = 0.f;
    for (int n = threadIdx.y; n < N_; n += 16) {
        float v = xb[(size_t)n * Cx + c];
        s  += v;
        s2 += v * v;
    }
    __shared__ float sh_s [16][33];
    __shared__ float sh_s2[16][33];
    sh_s [threadIdx.y][threadIdx.x] = s;
    sh_s2[threadIdx.y][threadIdx.x] = s2;
    __syncthreads();
    if (threadIdx.y == 0) {
        #pragma unroll
        for (int i = 1; i < 16; i++) {
            s  += sh_s [i][threadIdx.x];
            s2 += sh_s2[i][threadIdx.x];
        }
        float m   = s * (1.0f / N_);
        float var = s2 * (1.0f / N_) - m * m;
        float r   = rsqrtf(var + EPS_NORM);
        if (WHICH == 0) { g_mc [b * Cx + c] = m; g_rc [b * Cx + c] = r; }
        if (WHICH == 1) { g_mcc[b * Cx + c] = m; g_rcc[b * Cx + c] = r; }
        if (WHICH == 2) { g_mcs[b * Cx + c] = m; g_rcs[b * Cx + c] = r; }
    }
}

// ---------------------------------------------------------------------------
// Projection GEMM:  DST = norm(A) @ W + bias  (one batch)
// BM=128, BN=128, BK=16, 256 thr, 8x8 microtile.
// Smem double-buffered (global prefetch) + explicit LDS register ping-pong
// (prefetch k+1's fragments while k's FFMAs execute) to kill the ~29cyc
// LDS short-scoreboard stall that capped fma pipe at 46%.
// ---------------------------------------------------------------------------
template<int NORM, int DST>
__global__ __launch_bounds__(256)
void proj_kernel(const float* __restrict__ A,
                 const float* __restrict__ W,
                 const float* __restrict__ bias,
                 int b, int Nn, int K)
{
    __shared__ float As[2][16][128 + 4];
    __shared__ float Bs[2][16][128 + 4];

    float* Cb = (DST == 0) ? g_Q : (DST == 1) ? g_K : g_V;
    const float* mA = (NORM == 1) ? (g_mcc + (size_t)b * K)
                    : (NORM == 2) ? (g_mcs + (size_t)b * K) : nullptr;
    const float* rA = (NORM == 1) ? (g_rcc + (size_t)b * K)
                    : (NORM == 2) ? (g_rcs + (size_t)b * K) : nullptr;

    int m0 = blockIdx.y * 128;
    int n0 = blockIdx.x * 128;
    int tid = threadIdx.x;
    int a_k = tid & 15, a_m = tid >> 4;
    int b_n = tid & 127, b_kk = tid >> 7;
    int tc  = tid & 15, tr  = tid >> 4;

    float a_st[8], b_st[8];
    float acc[8][8];
    #pragma unroll
    for (int i = 0; i < 8; i++)
        #pragma unroll
        for (int j = 0; j < 8; j++) acc[i][j] = 0.f;

    // prologue: tile 0 -> buffer 0
    {
        float nm = 0.f, nr = 1.f;
        if (NORM) { nm = mA[a_k]; nr = rA[a_k]; }
        #pragma unroll
        for (int i = 0; i < 8; i++) {
            float v = A[(size_t)(m0 + a_m + i * 16) * K + a_k];
            a_st[i] = NORM ? (v - nm) * nr : v;
        }
        #pragma unroll
        for (int i = 0; i < 8; i++)
            b_st[i] = (n0 + b_n < Nn)
                      ? W[(size_t)(b_kk + i * 2) * Nn + n0 + b_n] : 0.f;
        #pragma unroll
        for (int i = 0; i < 8; i++) As[0][a_k][a_m + i * 16] = a_st[i];
        #pragma unroll
        for (int i = 0; i < 8; i++) Bs[0][b_kk + i * 2][b_n] = b_st[i];
    }
    __syncthreads();

    int nT = K / 16;
    for (int t = 0; t < nT; t++) {
        int cur = t & 1;
        if (t + 1 < nT) {
            int k0 = (t + 1) * 16;
            float nm = 0.f, nr = 1.f;
            if (NORM) { nm = mA[k0 + a_k]; nr = rA[k0 + a_k]; }
            #pragma unroll
            for (int i = 0; i < 8; i++) {
                float v = A[(size_t)(m0 + a_m + i * 16) * K + k0 + a_k];
                a_st[i] = NORM ? (v - nm) * nr : v;
            }
            #pragma unroll
            for (int i = 0; i < 8; i++)
                b_st[i] = (n0 + b_n < Nn)
                          ? W[(size_t)(k0 + b_kk + i * 2) * Nn + n0 + b_n] : 0.f;
        }
        // compute with explicit LDS ping-pong
        {
            float ra[2][8], rb[2][8];
            #pragma unroll
            for (int i = 0; i < 8; i++) ra[0][i] = As[cur][0][tr * 8 + i];
            #pragma unroll
            for (int j = 0; j < 8; j++) rb[0][j] = Bs[cur][0][tc * 8 + j];
            #pragma unroll
            for (int k = 0; k < 16; k++) {
                int pp = k & 1;
                if (k < 15) {
                    #pragma unroll
                    for (int i = 0; i < 8; i++)
                        ra[pp ^ 1][i] = As[cur][k + 1][tr * 8 + i];
                    #pragma unroll
                    for (int j = 0; j < 8; j++)
                        rb[pp ^ 1][j] = Bs[cur][k + 1][tc * 8 + j];
                }
                #pragma unroll
                for (int i = 0; i < 8; i++)
                    #pragma unroll
                    for (int j = 0; j < 8; j++)
                        acc[i][j] += ra[pp][i] * rb[pp][j];
            }
        }
        if (t + 1 < nT) {
            #pragma unroll
            for (int i = 0; i < 8; i++) As[cur ^ 1][a_k][a_m + i * 16] = a_st[i];
            #pragma unroll
            for (int i = 0; i < 8; i++) Bs[cur ^ 1][b_kk + i * 2][b_n] = b_st[i];
        }
        __syncthreads();
    }

    #pragma unroll
    for (int i = 0; i < 8; i++) {
        int m = m0 + tr * 8 + i;
        #pragma unroll
        for (int j = 0; j < 8; j++) {
            int n = n0 + tc * 8 + j;
            if (n < Nn)
                Cb[(size_t)m * Nn + n] = acc[i][j] + bias[n];
        }
    }
}

// ---------------------------------------------------------------------------
// Logits chunk:  g_Ablk = Q[chunk] @ K^T.  Same pipelining scheme.
// ---------------------------------------------------------------------------
__global__ __launch_bounds__(256)
void qkt_kernel(int mblk)
{
    __shared__ float As[2][16][128 + 4];
    __shared__ float Bs[2][16][128 + 4];

    int mloc0 = blockIdx.y * 128;
    int m0 = mblk * CHUNK + mloc0;
    int n0 = blockIdx.x * 128;
    int tid = threadIdx.x;
    int a_k = tid & 15, a_m = tid >> 4;
    int tc  = tid & 15, tr  = tid >> 4;

    float a_st[8], b_st[8];
    float acc[8][8];
    #pragma unroll
    for (int i = 0; i < 8; i++)
        #pragma unroll
        for (int j = 0; j < 8; j++) acc[i][j] = 0.f;

    {
        #pragma unroll
        for (int i = 0; i < 8; i++) {
            int r = a_m + i * 16;
            a_st[i] = g_Q[(size_t)(m0 + r) * C1_ + a_k];
            b_st[i] = g_K[(size_t)(n0 + r) * C1_ + a_k];
        }
        #pragma unroll
        for (int i = 0; i < 8; i++) {
            As[0][a_k][a_m + i * 16] = a_st[i];
            Bs[0][a_k][a_m + i * 16] = b_st[i];
        }
    }
    __syncthreads();

    const int nT = C1_ / 16;   // 60
    for (int t = 0; t < nT; t++) {
        int cur = t & 1;
        if (t + 1 < nT) {
            int k0 = (t + 1) * 16;
            #pragma unroll
            for (int i = 0; i < 8; i++) {
                int r = a_m + i * 16;
                a_st[i] = g_Q[(size_t)(m0 + r) * C1_ + k0 + a_k];
                b_st[i] = g_K[(size_t)(n0 + r) * C1_ + k0 + a_k];
            }
        }
        {
            float ra[2][8], rb[2][8];
            #pragma unroll
            for (int i = 0; i < 8; i++) ra[0][i] = As[cur][0][tr * 8 + i];
            #pragma unroll
            for (int j = 0; j < 8; j++) rb[0][j] = Bs[cur][0][tc * 8 + j];
            #pragma unroll
            for (int k = 0; k < 16; k++) {
                int pp = k & 1;
                if (k < 15) {
                    #pragma unroll
                    for (int i = 0; i < 8; i++)
                        ra[pp ^ 1][i] = As[cur][k + 1][tr * 8 + i];
                    #pragma unroll
                    for (int j = 0; j < 8; j++)
                        rb[pp ^ 1][j] = Bs[cur][k + 1][tc * 8 + j];
                }
                #pragma unroll
                for (int i = 0; i < 8; i++)
                    #pragma unroll
                    for (int j = 0; j < 8; j++)
                        acc[i][j] += ra[pp][i] * rb[pp][j];
            }
        }
        if (t + 1 < nT) {
            #pragma unroll
            for (int i = 0; i < 8; i++) {
                As[cur ^ 1][a_k][a_m + i * 16] = a_st[i];
                Bs[cur ^ 1][a_k][a_m + i * 16] = b_st[i];
            }
        }
        __syncthreads();
    }

    #pragma unroll
    for (int i = 0; i < 8; i++) {
        size_t row = (size_t)(mloc0 + tr * 8 + i) * N_;
        int n = n0 + tc * 8;
        float4 v0, v1;
        v0.x = acc[i][0]; v0.y = acc[i][1]; v0.z = acc[i][2]; v0.w = acc[i][3];
        v1.x = acc[i][4]; v1.y = acc[i][5]; v1.z = acc[i][6]; v1.w = acc[i][7];
        *(float4*)(g_Ablk + row + n)     = v0;
        *(float4*)(g_Ablk + row + n + 4) = v1;
    }
}

// ---------------------------------------------------------------------------
// Row softmax over g_Ablk (CHUNK rows of 4096), in place.
// ---------------------------------------------------------------------------
__global__ __launch_bounds__(256)
void softmax_kernel()
{
    float* a = g_Ablk + (size_t)blockIdx.x * N_;
    int t = threadIdx.x;

    float v[16];
    float mx = -3.0e38f;
    #pragma unroll
    for (int i = 0; i < 16; i++) {
        v[i] = a[t + i * 256];
        mx = fmaxf(mx, v[i]);
    }
    __shared__ float red[256];
    red[t] = mx;
    __syncthreads();
    #pragma unroll
    for (int s = 128; s > 0; s >>= 1) {
        if (t < s) red[t] = fmaxf(red[t], red[t + s]);
        __syncthreads();
    }
    mx = red[0];
    __syncthreads();

    float sum = 0.f;
    #pragma unroll
    for (int i = 0; i < 16; i++) {
        v[i] = __expf(v[i] - mx);
        sum += v[i];
    }
    red[t] = sum;
    __syncthreads();
    #pragma unroll
    for (int s = 128; s > 0; s >>= 1) {
        if (t < s) red[t] += red[t + s];
        __syncthreads();
    }
    float inv = 1.0f / red[0];
    #pragma unroll
    for (int i = 0; i < 16; i++)
        a[t + i * 256] = v[i] * inv;
}

// ---------------------------------------------------------------------------
// Dual GEMM + epilogue:
//   M = A@V, E2 = A@(V*V); out = sqrt(max(E2-M*M,eps))*norm(content) + M
// BM=128, BN=64, BK=16; 8x4 dual microtile; same pipelining scheme.
// ---------------------------------------------------------------------------
__global__ __launch_bounds__(256)
void av_epi_kernel(const float* __restrict__ content,
                   float* __restrict__ out, int b, int mblk)
{
    __shared__ float As[2][16][128 + 4];
    __shared__ float Vs[2][16][64];

    int mloc0 = blockIdx.y * 128;
    int n0 = blockIdx.x * 64;
    int tid = threadIdx.x;
    int a_k = tid & 15, a_m = tid >> 4;
    int v_n = tid & 63, v_k = tid >> 6;
    int tc  = tid & 15, tr  = tid >> 4;

    float a_st[8], v_st[4];
    float accM[8][4], accE[8][4];
    #pragma unroll
    for (int i = 0; i < 8; i++)
        #pragma unroll
        for (int j = 0; j < 4; j++) { accM[i][j] = 0.f; accE[i][j] = 0.f; }

    {
        #pragma unroll
        for (int i = 0; i < 8; i++)
            a_st[i] = g_Ablk[(size_t)(mloc0 + a_m + i * 16) * N_ + a_k];
        #pragma unroll
        for (int i = 0; i < 4; i++)
            v_st[i] = g_V[(size_t)(v_k + i * 4) * C_ + n0 + v_n];
        #pragma unroll
        for (int i = 0; i < 8; i++) As[0][a_k][a_m + i * 16] = a_st[i];
        #pragma unroll
        for (int i = 0; i < 4; i++) Vs[0][v_k + i * 4][v_n] = v_st[i];
    }
    __syncthreads();

    const int nT = N_ / 16;    // 256
    for (int t = 0; t < nT; t++) {
        int cur = t & 1;
        if (t + 1 < nT) {
            int k0 = (t + 1) * 16;
            #pragma unroll
            for (int i = 0; i < 8; i++)
                a_st[i] = g_Ablk[(size_t)(mloc0 + a_m + i * 16) * N_ + k0 + a_k];
            #pragma unroll
            for (int i = 0; i < 4; i++)
                v_st[i] = g_V[(size_t)(k0 + v_k + i * 4) * C_ + n0 + v_n];
        }
        {
            float ra[2][8], rb[2][4];
            #pragma unroll
            for (int i = 0; i < 8; i++) ra[0][i] = As[cur][0][tr * 8 + i];
            #pragma unroll
            for (int j = 0; j < 4; j++) rb[0][j] = Vs[cur][0][tc * 4 + j];
            #pragma unroll
            for (int k = 0; k < 16; k++) {
                int pp = k & 1;
                if (k < 15) {
                    #pragma unroll
                    for (int i = 0; i < 8; i++)
                        ra[pp ^ 1][i] = As[cur][k + 1][tr * 8 + i];
                    #pragma unroll
                    for (int j = 0; j < 4; j++)
                        rb[pp ^ 1][j] = Vs[cur][k + 1][tc * 4 + j];
                }
                float rb2[4];
                #pragma unroll
                for (int j = 0; j < 4; j++) rb2[j] = rb[pp][j] * rb[pp][j];
                #pragma unroll
                for (int i = 0; i < 8; i++)
                    #pragma unroll
                    for (int j = 0; j < 4; j++) {
                        accM[i][j] += ra[pp][i] * rb[pp][j];
                        accE[i][j] += ra[pp][i] * rb2[j];
                    }
            }
        }
        if (t + 1 < nT) {
            #pragma unroll
            for (int i = 0; i < 8; i++) As[cur ^ 1][a_k][a_m + i * 16] = a_st[i];
            #pragma unroll
            for (int i = 0; i < 4; i++) Vs[cur ^ 1][v_k + i * 4][v_n] = v_st[i];
        }
        __syncthreads();
    }

    #pragma unroll
    for (int i = 0; i < 8; i++) {
        int m_global = mblk * CHUNK + mloc0 + tr * 8 + i;
        int c = n0 + tc * 4;
        size_t idx = ((size_t)b * N_ + m_global) * (size_t)C_ + c;
        float oo[4];
        #pragma unroll
        for (int j = 0; j < 4; j++) {
            float Mv = accM[i][j];
            float E2 = accE[i][j];
            float S  = sqrtf(fmaxf(E2 - Mv * Mv, EPS_VAR));
            float nc = (content[idx + j] - g_mc[b * C_ + c + j]) * g_rc[b * C_ + c + j];
            oo[j] = S * nc + Mv;
        }
        float4 o; o.x = oo[0]; o.y = oo[1]; o.z = oo[2]; o.w = oo[3];
        *(float4*)(out + idx) = o;
    }
}

// ---------------------------------------------------------------------------
// Launch — pure kernel launches (graph-capture safe).
// ---------------------------------------------------------------------------
extern "C" void kernel_launch(void* const* d_in, const int* in_sizes, int n_in,
                              void* d_out, int out_size)
{
    const float* content   = (const float*)d_in[0];
    const float* style     = (const float*)d_in[1];
    const float* comb_cont = (const float*)d_in[2];
    const float* comb_sty  = (const float*)d_in[3];
    const float* Wq        = (const float*)d_in[4];
    const float* bq        = (const float*)d_in[5];
    const float* Wk        = (const float*)d_in[6];
    const float* bk        = (const float*)d_in[7];
    const float* Wv        = (const float*)d_in[8];
    const float* bv        = (const float*)d_in[9];
    float* out = (float*)d_out;

    dim3 blk_stats(32, 16);
    stats_kernel<0><<<dim3(C_  / 32, B_), blk_stats>>>(content,   C_);
    stats_kernel<1><<<dim3(C1_ / 32, B_), blk_stats>>>(comb_cont, C1_);
    stats_kernel<2><<<dim3(C1_ / 32, B_), blk_stats>>>(comb_sty,  C1_);

    for (int b = 0; b < B_; b++) {
        proj_kernel<1, 0><<<dim3(8, N_ / 128), 256>>>(
            comb_cont + (size_t)b * N_ * C1_, Wq, bq, b, C1_, C1_);
        proj_kernel<2, 1><<<dim3(8, N_ / 128), 256>>>(
            comb_sty + (size_t)b * N_ * C1_, Wk, bk, b, C1_, C1_);
        proj_kernel<0, 2><<<dim3(4, N_ / 128), 256>>>(
            style + (size_t)b * N_ * C_, Wv, bv, b, C_, C_);

        for (int mblk = 0; mblk < N_ / CHUNK; mblk++) {
            qkt_kernel<<<dim3(N_ / 128, CHUNK / 128), 256>>>(mblk);
            softmax_kernel<<<CHUNK, 256>>>();
            av_epi_kernel<<<dim3(C_ / 64, CHUNK / 128), 256>>>(content, out, b, mblk);
        }
    }
}